// round 16
// baseline (speedup 1.0000x reference)
#include <cuda_runtime.h>
#include <math_constants.h>
#include <cstdint>

#define SDIM 2048
#define BDIM 32
#define HDIM 1024

#define KS 16          // k-splits
#define KT (HDIM / KS) // 64 k per split
#define HT 128         // h per block tile (8 tiles)

// Scratch (no device allocs allowed)
__device__ float g_part[KS * BDIM * HDIM];  // split-K partials (2 MB)
__device__ float g_u[BDIM * HDIM];          // u = hidden @ W
__device__ float g_scores[BDIM * SDIM];     // scores[b,s]

// --- PDL primitives -------------------------------------------------------
__device__ __forceinline__ void grid_wait() {
    asm volatile("griddepcontrol.wait;" ::: "memory");
}
__device__ __forceinline__ void grid_trigger() {
    asm volatile("griddepcontrol.launch_dependents;");
}
__device__ __forceinline__ unsigned int smem_u32(const void* p) {
    unsigned int a;
    asm("{ .reg .u64 t; cvta.to.shared.u64 t, %1; cvt.u32.u64 %0, t; }"
        : "=r"(a) : "l"(p));
    return a;
}

// ---------------------------------------------------------------------------
// Kernel 1: split-K tiled GEMM u_part = hidden[:, krange] @ W[krange, htile]
// grid (8 h-tiles, 16 k-splits) = 128 blocks, 512 threads. Entry-trigger.
// ---------------------------------------------------------------------------
__global__ __launch_bounds__(512) void proj_kernel(
    const float* __restrict__ hidden, const float* __restrict__ W) {
    grid_trigger();   // release chain immediately (consumers gate on grid_wait)

    __shared__ float4 sW[KT * (HT / 4)];   // 32 KB
    __shared__ float  sH[BDIM * KT];       // 8 KB

    const int h0 = blockIdx.x * HT;
    const int k0 = blockIdx.y * KT;
    const int tid = threadIdx.x;

    const float4* __restrict__ Wg = reinterpret_cast<const float4*>(W);
#pragma unroll
    for (int i = 0; i < (KT * HT / 4) / 512; ++i) {   // 4 iters
        int idx = tid + i * 512;
        int kk = idx >> 5;
        int c  = idx & 31;
        sW[idx] = Wg[(size_t)(k0 + kk) * (HDIM / 4) + (h0 >> 2) + c];
    }
#pragma unroll
    for (int i = 0; i < (BDIM * KT) / 512; ++i) {     // 4 iters
        int idx = tid + i * 512;
        int bb = idx >> 6;
        int kk = idx & 63;
        sH[idx] = hidden[bb * HDIM + k0 + kk];
    }
    __syncthreads();

    const int lane = tid & 31;
    const int b0 = (tid >> 5) * 2;      // 16 warps x 2 b

    float4 acc0 = {0,0,0,0}, acc1 = {0,0,0,0};
#pragma unroll 16
    for (int k = 0; k < KT; ++k) {
        float4 w4 = sW[k * 32 + lane];
        float h0v = sH[(b0 + 0) * KT + k];
        float h1v = sH[(b0 + 1) * KT + k];
        acc0.x = fmaf(h0v, w4.x, acc0.x); acc0.y = fmaf(h0v, w4.y, acc0.y);
        acc0.z = fmaf(h0v, w4.z, acc0.z); acc0.w = fmaf(h0v, w4.w, acc0.w);
        acc1.x = fmaf(h1v, w4.x, acc1.x); acc1.y = fmaf(h1v, w4.y, acc1.y);
        acc1.z = fmaf(h1v, w4.z, acc1.z); acc1.w = fmaf(h1v, w4.w, acc1.w);
    }

    float4* __restrict__ part4 = reinterpret_cast<float4*>(
        g_part + (size_t)blockIdx.y * BDIM * HDIM);
    const int hbase4 = (h0 >> 2) + lane;
    part4[(b0 + 0) * (HDIM / 4) + hbase4] = acc0;
    part4[(b0 + 1) * (HDIM / 4) + hbase4] = acc1;
}

// ---------------------------------------------------------------------------
// Kernel 1b: fold split-K partials (fixed order -> deterministic).
// ---------------------------------------------------------------------------
__global__ __launch_bounds__(256) void reduce_kernel() {
    grid_trigger();   // release score immediately
    grid_wait();      // proj complete; g_part visible

    const int idx4 = blockIdx.x * 256 + threadIdx.x;   // float4 idx, 0..8191
    float4 s4 = {0, 0, 0, 0};
#pragma unroll
    for (int j = 0; j < KS; ++j) {
        float4 p = __ldcs(reinterpret_cast<const float4*>(
            g_part + (size_t)j * BDIM * HDIM) + idx4);
        s4.x += p.x; s4.y += p.y; s4.z += p.z; s4.w += p.w;
    }
    reinterpret_cast<float4*>(g_u)[idx4] = s4;
}

// ---------------------------------------------------------------------------
// Kernel 2: scores[b,s] = u[b] . enc[s,b,:] — 268 MB HBM stream.
// cp.async prefetch of the block's full 32 KB into smem BEFORE grid_wait:
// zero register cost -> ~6-7 blocks/SM resident -> ~29 MB in flight while
// proj/reduce still run. Consumption: e from smem, u from L2.
// ---------------------------------------------------------------------------
__global__ __launch_bounds__(256) void score_kernel(const float* __restrict__ enc) {
    grid_trigger();   // release softmax grid early (it waits on our completion)

    __shared__ float4 se[8 * 8 * 32];   // [warp][j][lane] = 32 KB

    const int tid = threadIdx.x;
    const int w = tid >> 5;
    const int lane = tid & 31;
    const int warp = (blockIdx.x << 3) + w;
    const int b = warp & (BDIM - 1);
    const int s = warp >> 5;

    const float4* __restrict__ erow =
        reinterpret_cast<const float4*>(enc + (size_t)warp * HDIM);

    // ---- async prefetch: global -> smem, proceeds while we spin in wait ----
    const unsigned int sbase = smem_u32(&se[(w * 8) * 32 + lane]);
#pragma unroll
    for (int j = 0; j < 8; ++j) {
        asm volatile("cp.async.cg.shared.global [%0], [%1], 16;"
                     :: "r"(sbase + j * 32 * 16), "l"(&erow[j * 32 + lane]));
    }
    asm volatile("cp.async.commit_group;" ::: "memory");

    grid_wait();   // reduce complete; g_u visible

    asm volatile("cp.async.wait_group 0;" ::: "memory");

    const float4* __restrict__ urow =
        reinterpret_cast<const float4*>(g_u + b * HDIM);

    float acc = 0.0f;
#pragma unroll
    for (int j = 0; j < 8; ++j) {
        float4 u = __ldg(&urow[j * 32 + lane]);          // cached, L2-resident
        float4 e = se[(w * 8 + j) * 32 + lane];          // conflict-free LDS
        acc = fmaf(e.x, u.x, acc);
        acc = fmaf(e.y, u.y, acc);
        acc = fmaf(e.z, u.z, acc);
        acc = fmaf(e.w, u.w, acc);
    }
#pragma unroll
    for (int off = 16; off > 0; off >>= 1)
        acc += __shfl_xor_sync(0xFFFFFFFFu, acc, off);

    if (lane == 0) g_scores[b * SDIM + s] = acc;
}

// ---------------------------------------------------------------------------
// Kernel 3: softmax over s per b. 32 blocks x 1024 threads, PDL-prelaunched.
// (hidden.bias term is constant per b -> invariant under softmax -> dropped.)
// ---------------------------------------------------------------------------
__global__ __launch_bounds__(1024) void softmax_kernel(float* __restrict__ out) {
    grid_wait();   // score complete; g_scores visible

    const int b = blockIdx.x;
    const int tid = threadIdx.x;
    const float* __restrict__ row = g_scores + b * SDIM;

    __shared__ float sred[32];

    float v0 = row[tid];
    float v1 = row[tid + 1024];
    float vmax = fmaxf(v0, v1);
#pragma unroll
    for (int off = 16; off > 0; off >>= 1)
        vmax = fmaxf(vmax, __shfl_xor_sync(0xFFFFFFFFu, vmax, off));
    if ((tid & 31) == 0) sred[tid >> 5] = vmax;
    __syncthreads();
    if (tid < 32) {
        float v = sred[tid];
#pragma unroll
        for (int off = 16; off > 0; off >>= 1)
            v = fmaxf(v, __shfl_xor_sync(0xFFFFFFFFu, v, off));
        sred[0] = v;
    }
    __syncthreads();
    vmax = sred[0];
    __syncthreads();

    v0 = __expf(v0 - vmax);
    v1 = __expf(v1 - vmax);
    float lsum = v0 + v1;
#pragma unroll
    for (int off = 16; off > 0; off >>= 1)
        lsum += __shfl_xor_sync(0xFFFFFFFFu, lsum, off);
    if ((tid & 31) == 0) sred[tid >> 5] = lsum;
    __syncthreads();
    if (tid < 32) {
        float v = sred[tid];
#pragma unroll
        for (int off = 16; off > 0; off >>= 1)
            v += __shfl_xor_sync(0xFFFFFFFFu, v, off);
        sred[0] = v;
    }
    __syncthreads();
    const float inv = 1.0f / sred[0];

    out[b * SDIM + tid]        = v0 * inv;
    out[b * SDIM + tid + 1024] = v1 * inv;
}

// ---------------------------------------------------------------------------
extern "C" void kernel_launch(void* const* d_in, const int* in_sizes, int n_in,
                              void* d_out, int out_size) {
    const float* hidden = (const float*)d_in[0];  // [B,H]
    const float* enc    = (const float*)d_in[1];  // [S,B,H]
    const float* W      = (const float*)d_in[2];  // [H,H]
    float* out = (float*)d_out;                   // [1,B,S]

    // First kernel: ordinary launch (entry-triggers the PDL chain).
    dim3 pg(HDIM / HT, KS);                       // (8, 16)
    proj_kernel<<<pg, 512>>>(hidden, W);

    cudaLaunchAttribute pdl[1];
    pdl[0].id = cudaLaunchAttributeProgrammaticStreamSerialization;
    pdl[0].val.programmaticStreamSerializationAllowed = 1;

    cudaLaunchConfig_t cfg = {};
    cfg.stream = 0;
    cfg.attrs = pdl;
    cfg.numAttrs = 1;

    cfg.gridDim = dim3((BDIM * HDIM / 4) / 256);  // 32 blocks
    cfg.blockDim = dim3(256);
    cudaLaunchKernelEx(&cfg, reduce_kernel);

    cfg.gridDim = dim3(SDIM * BDIM / 8);          // 8192 blocks
    cfg.blockDim = dim3(256);
    cudaLaunchKernelEx(&cfg, score_kernel, enc);

    cfg.gridDim = dim3(BDIM);                     // 32 blocks
    cfg.blockDim = dim3(1024);
    cudaLaunchKernelEx(&cfg, softmax_kernel, out);
}

// round 17
// speedup vs baseline: 1.0758x; 1.0758x over previous
#include <cuda_runtime.h>
#include <math_constants.h>
#include <cstdint>

#define SDIM 2048
#define BDIM 32
#define HDIM 1024

#define KS 16          // k-splits
#define KT (HDIM / KS) // 64 k per split
#define HT 128         // h per block tile (8 tiles)

// Scratch (no device allocs allowed)
__device__ float g_part[KS * BDIM * HDIM];  // split-K partials (2 MB)
__device__ float g_u[BDIM * HDIM];          // u = hidden @ W
__device__ float g_scores[BDIM * SDIM];     // scores[b,s]

// --- PDL primitives -------------------------------------------------------
__device__ __forceinline__ void grid_wait() {
    asm volatile("griddepcontrol.wait;" ::: "memory");
}
__device__ __forceinline__ void grid_trigger() {
    asm volatile("griddepcontrol.launch_dependents;");
}

// ---------------------------------------------------------------------------
// Kernel 1: split-K tiled GEMM u_part = hidden[:, krange] @ W[krange, htile]
// grid (8 h-tiles, 16 k-splits) = 128 blocks, 512 threads. Entry-trigger.
// ---------------------------------------------------------------------------
__global__ __launch_bounds__(512) void proj_kernel(
    const float* __restrict__ hidden, const float* __restrict__ W) {
    grid_trigger();   // release chain immediately (consumers gate on grid_wait)

    __shared__ float4 sW[KT * (HT / 4)];   // 32 KB
    __shared__ float  sH[BDIM * KT];       // 8 KB

    const int h0 = blockIdx.x * HT;
    const int k0 = blockIdx.y * KT;
    const int tid = threadIdx.x;

    const float4* __restrict__ Wg = reinterpret_cast<const float4*>(W);
#pragma unroll
    for (int i = 0; i < (KT * HT / 4) / 512; ++i) {   // 4 iters
        int idx = tid + i * 512;
        int kk = idx >> 5;
        int c  = idx & 31;
        sW[idx] = Wg[(size_t)(k0 + kk) * (HDIM / 4) + (h0 >> 2) + c];
    }
#pragma unroll
    for (int i = 0; i < (BDIM * KT) / 512; ++i) {     // 4 iters
        int idx = tid + i * 512;
        int bb = idx >> 6;
        int kk = idx & 63;
        sH[idx] = hidden[bb * HDIM + k0 + kk];
    }
    __syncthreads();

    const int lane = tid & 31;
    const int b0 = (tid >> 5) * 2;      // 16 warps x 2 b

    float4 acc0 = {0,0,0,0}, acc1 = {0,0,0,0};
#pragma unroll 16
    for (int k = 0; k < KT; ++k) {
        float4 w4 = sW[k * 32 + lane];
        float h0v = sH[(b0 + 0) * KT + k];
        float h1v = sH[(b0 + 1) * KT + k];
        acc0.x = fmaf(h0v, w4.x, acc0.x); acc0.y = fmaf(h0v, w4.y, acc0.y);
        acc0.z = fmaf(h0v, w4.z, acc0.z); acc0.w = fmaf(h0v, w4.w, acc0.w);
        acc1.x = fmaf(h1v, w4.x, acc1.x); acc1.y = fmaf(h1v, w4.y, acc1.y);
        acc1.z = fmaf(h1v, w4.z, acc1.z); acc1.w = fmaf(h1v, w4.w, acc1.w);
    }

    float4* __restrict__ part4 = reinterpret_cast<float4*>(
        g_part + (size_t)blockIdx.y * BDIM * HDIM);
    const int hbase4 = (h0 >> 2) + lane;
    part4[(b0 + 0) * (HDIM / 4) + hbase4] = acc0;
    part4[(b0 + 1) * (HDIM / 4) + hbase4] = acc1;
}

// ---------------------------------------------------------------------------
// Kernel 1b: fold split-K partials (fixed order -> deterministic).
// ---------------------------------------------------------------------------
__global__ __launch_bounds__(256) void reduce_kernel() {
    grid_trigger();   // release score immediately
    grid_wait();      // proj complete; g_part visible

    const int idx4 = blockIdx.x * 256 + threadIdx.x;   // float4 idx, 0..8191
    float4 s4 = {0, 0, 0, 0};
#pragma unroll
    for (int j = 0; j < KS; ++j) {
        float4 p = __ldcs(reinterpret_cast<const float4*>(
            g_part + (size_t)j * BDIM * HDIM) + idx4);
        s4.x += p.x; s4.y += p.y; s4.z += p.z; s4.w += p.w;
    }
    reinterpret_cast<float4*>(g_u)[idx4] = s4;
}

// ---------------------------------------------------------------------------
// Kernel 2: scores[b,s] = u[b] . enc[s,b,:] — 268 MB HBM stream.
// Register prefetch of enc BEFORE grid_wait (proven R14 form): resident waves
// stream enc from DRAM while proj/reduce still run. Entry-trigger so the
// softmax grid ramps during our 37us instead of after.
// ---------------------------------------------------------------------------
__global__ __launch_bounds__(256) void score_kernel(const float* __restrict__ enc) {
    grid_trigger();   // softmax grid launches now; its wait gates on our finish

    const int warp = (blockIdx.x * blockDim.x + threadIdx.x) >> 5;
    const int lane = threadIdx.x & 31;

    const int b = warp & (BDIM - 1);
    const int s = warp >> 5;

    const float4* __restrict__ erow =
        reinterpret_cast<const float4*>(enc + (size_t)warp * HDIM);

    // ---- prefetch: issue all enc loads before waiting on g_u ----
    float4 e[8];
#pragma unroll
    for (int j = 0; j < 8; ++j)
        e[j] = __ldcs(&erow[j * 32 + lane]);

    grid_wait();   // reduce complete; g_u visible

    const float4* __restrict__ urow =
        reinterpret_cast<const float4*>(g_u + b * HDIM);

    float acc = 0.0f;
#pragma unroll
    for (int j = 0; j < 8; ++j) {
        float4 u = __ldg(&urow[j * 32 + lane]);    // cached, L1/L2-resident
        acc = fmaf(e[j].x, u.x, acc);
        acc = fmaf(e[j].y, u.y, acc);
        acc = fmaf(e[j].z, u.z, acc);
        acc = fmaf(e[j].w, u.w, acc);
    }
#pragma unroll
    for (int off = 16; off > 0; off >>= 1)
        acc += __shfl_xor_sync(0xFFFFFFFFu, acc, off);

    if (lane == 0) g_scores[b * SDIM + s] = acc;
}

// ---------------------------------------------------------------------------
// Kernel 3: softmax over s per b. 32 blocks x 1024 threads, PDL-prelaunched.
// (hidden.bias term is constant per b -> invariant under softmax -> dropped.)
// ---------------------------------------------------------------------------
__global__ __launch_bounds__(1024) void softmax_kernel(float* __restrict__ out) {
    grid_wait();   // score complete; g_scores visible

    const int b = blockIdx.x;
    const int tid = threadIdx.x;
    const float* __restrict__ row = g_scores + b * SDIM;

    __shared__ float sred[32];

    float v0 = row[tid];
    float v1 = row[tid + 1024];
    float vmax = fmaxf(v0, v1);
#pragma unroll
    for (int off = 16; off > 0; off >>= 1)
        vmax = fmaxf(vmax, __shfl_xor_sync(0xFFFFFFFFu, vmax, off));
    if ((tid & 31) == 0) sred[tid >> 5] = vmax;
    __syncthreads();
    if (tid < 32) {
        float v = sred[tid];
#pragma unroll
        for (int off = 16; off > 0; off >>= 1)
            v = fmaxf(v, __shfl_xor_sync(0xFFFFFFFFu, v, off));
        sred[0] = v;
    }
    __syncthreads();
    vmax = sred[0];
    __syncthreads();

    v0 = __expf(v0 - vmax);
    v1 = __expf(v1 - vmax);
    float lsum = v0 + v1;
#pragma unroll
    for (int off = 16; off > 0; off >>= 1)
        lsum += __shfl_xor_sync(0xFFFFFFFFu, lsum, off);
    if ((tid & 31) == 0) sred[tid >> 5] = lsum;
    __syncthreads();
    if (tid < 32) {
        float v = sred[tid];
#pragma unroll
        for (int off = 16; off > 0; off >>= 1)
            v += __shfl_xor_sync(0xFFFFFFFFu, v, off);
        sred[0] = v;
    }
    __syncthreads();
    const float inv = 1.0f / sred[0];

    out[b * SDIM + tid]        = v0 * inv;
    out[b * SDIM + tid + 1024] = v1 * inv;
}

// ---------------------------------------------------------------------------
extern "C" void kernel_launch(void* const* d_in, const int* in_sizes, int n_in,
                              void* d_out, int out_size) {
    const float* hidden = (const float*)d_in[0];  // [B,H]
    const float* enc    = (const float*)d_in[1];  // [S,B,H]
    const float* W      = (const float*)d_in[2];  // [H,H]
    float* out = (float*)d_out;                   // [1,B,S]

    // First kernel: ordinary launch (entry-triggers the PDL chain).
    dim3 pg(HDIM / HT, KS);                       // (8, 16)
    proj_kernel<<<pg, 512>>>(hidden, W);

    cudaLaunchAttribute pdl[1];
    pdl[0].id = cudaLaunchAttributeProgrammaticStreamSerialization;
    pdl[0].val.programmaticStreamSerializationAllowed = 1;

    cudaLaunchConfig_t cfg = {};
    cfg.stream = 0;
    cfg.attrs = pdl;
    cfg.numAttrs = 1;

    cfg.gridDim = dim3((BDIM * HDIM / 4) / 256);  // 32 blocks
    cfg.blockDim = dim3(256);
    cudaLaunchKernelEx(&cfg, reduce_kernel);

    cfg.gridDim = dim3(SDIM * BDIM / 8);          // 8192 blocks
    cfg.blockDim = dim3(256);
    cudaLaunchKernelEx(&cfg, score_kernel, enc);

    cfg.gridDim = dim3(BDIM);                     // 32 blocks
    cfg.blockDim = dim3(1024);
    cudaLaunchKernelEx(&cfg, softmax_kernel, out);
}